// round 1
// baseline (speedup 1.0000x reference)
#include <cuda_runtime.h>
#include <cuda_bf16.h>
#include <cstdint>

// Problem constants (fixed by the reference):
//   x:    (B=64, L=4096) int32 indices into VOCAB
//   w_in: (P=128, VOCAB=32000) float32, row-major
//   out:  (B, P, L) float32, out[b,p,l] = w_in[p, x[b,l]]
#define PB   128
#define VOC  32000
#define BB   64
#define LL   4096

// Scratch: transposed weight table w_t[v][p] (16.38 MB). __device__ global is
// the allowed scratch mechanism (no allocations permitted in kernel_launch).
__device__ float g_wt[(size_t)VOC * PB];

// ---------------------------------------------------------------------------
// Kernel A: tiled transpose w_in(P, VOC) -> g_wt(VOC, P).
// 32x32 tiles, smem padded to kill bank conflicts. Reads and writes both
// fully coalesced (128 B per warp).
// ---------------------------------------------------------------------------
__global__ void transpose_kernel(const float* __restrict__ w_in) {
    __shared__ float tile[32][33];
    const int v0 = blockIdx.x * 32;   // vocab tile origin (0..31968)
    const int p0 = blockIdx.y * 32;   // p tile origin (0,32,64,96)
    const int tx = threadIdx.x;       // 0..31
    const int ty = threadIdx.y;       // 0..7

    // Read: rows of w_in, coalesced along v.
    #pragma unroll
    for (int i = 0; i < 4; i++) {
        tile[ty + i * 8][tx] = w_in[(size_t)(p0 + ty + i * 8) * VOC + (v0 + tx)];
    }
    __syncthreads();

    // Write: rows of g_wt, coalesced along p.
    #pragma unroll
    for (int i = 0; i < 4; i++) {
        g_wt[(size_t)(v0 + ty + i * 8) * PB + (p0 + tx)] = tile[tx][ty + i * 8];
    }
}

// ---------------------------------------------------------------------------
// Kernel B: staged gather.
// Block: 256 threads, handles batch b = blockIdx.y, tokens [l0, l0+64).
// Phase 1: for each token t, load its 512 B column g_wt[v[t]][0..127]
//          coalesced (32 lanes x 4 loads) into smem s[t][p] (pad 129).
// Phase 2: remapped threads emit float4 (STG.128) stores coalesced along l.
// ---------------------------------------------------------------------------
#define LT   64          // tokens per block
#define SPAD 129         // smem row pitch in floats (conflict-free phase 2)

__global__ __launch_bounds__(256) void gather_kernel(
    const int* __restrict__ x, float* __restrict__ out) {
    __shared__ float s[LT * SPAD];   // 33,024 B
    __shared__ int   sv[LT];

    const int tid  = threadIdx.x;
    const int lane = tid & 31;
    const int warp = tid >> 5;
    const int b    = blockIdx.y;
    const int l0   = blockIdx.x * LT;

    if (tid < LT) sv[tid] = x[(size_t)b * LL + l0 + tid];
    __syncthreads();

    // Phase 1: 8 warps, each handles 8 tokens. Per token: 4 coalesced
    // 128 B loads from g_wt, 4 conflict-free stride-1 STS.
    #pragma unroll
    for (int i = 0; i < 8; i++) {
        const int t = warp + i * 8;
        const int v = sv[t];
        const float* __restrict__ src = &g_wt[(size_t)v * PB];
        float* __restrict__ dst = &s[t * SPAD];
        #pragma unroll
        for (int k = 0; k < 4; k++) {
            dst[lane + 32 * k] = src[lane + 32 * k];
        }
    }
    __syncthreads();

    // Phase 2: 2048 float4 outputs per block (128 p x 16 t-groups).
    // idx = tid + 256k; p = idx/16; tg = (idx%16)*4.
    // Within a warp: 16 lanes share p, sweeping t -> STG.128 coalesced
    // 256 B segments per p. LDS stride 4*129=516 -> 2-way conflict (ok).
    #pragma unroll
    for (int k = 0; k < 8; k++) {
        const int idx = tid + k * 256;
        const int p   = idx >> 4;
        const int tg  = (idx & 15) << 2;
        float4 o;
        o.x = s[(tg + 0) * SPAD + p];
        o.y = s[(tg + 1) * SPAD + p];
        o.z = s[(tg + 2) * SPAD + p];
        o.w = s[(tg + 3) * SPAD + p];
        *reinterpret_cast<float4*>(
            &out[((size_t)b * PB + p) * LL + l0 + tg]) = o;
    }
}

// ---------------------------------------------------------------------------
// Launch
// ---------------------------------------------------------------------------
extern "C" void kernel_launch(void* const* d_in, const int* in_sizes, int n_in,
                              void* d_out, int out_size) {
    const int*   x    = (const int*)d_in[0];     // (64, 4096) int32
    const float* w_in = (const float*)d_in[1];   // (128, 32000) fp32
    float*       out  = (float*)d_out;           // (64, 128, 4096) fp32

    (void)in_sizes; (void)n_in; (void)out_size;

    // A: transpose weights into g_wt (VOC/32 = 1000, P/32 = 4 tiles).
    transpose_kernel<<<dim3(VOC / 32, PB / 32), dim3(32, 8)>>>(w_in);

    // B: gather (L/LT = 64 l-chunks, B = 64 batches).
    gather_kernel<<<dim3(LL / LT, BB), 256>>>(x, out);
}